// round 11
// baseline (speedup 1.0000x reference)
#include <cuda_runtime.h>
#include <cuda_bf16.h>

// Problem constants: b=1, h=w=64, s=5, H=W=1024, ps=32, q=8
#define GRID_T   64
#define NTILES   (GRID_T * GRID_T)      // 4096
#define NSTROKE  5
#define IMG      1024
#define PLANE    (IMG * IMG)            // 1048576

__device__ __forceinline__ float tanh_(float x) {
    float r; asm("tanh.approx.f32 %0,%1;" : "=f"(r) : "f"(x)); return r;
}

// ---------------------------------------------------------------------------
// Single fused kernel. Block = one 16x16 padded-aligned cell, 64 threads
// (16x4), 4 pixels/thread (rows ty+{0,4,8,12}).
//
// Order of operations inside a block:
//   1. ALL threads issue their 6 canvas LDGs (latency hides under staging).
//   2. Warp 0 lanes 0..19 stage: inline prep (sigmoid/sincos), per-pass
//      counts exchanged via shfl (no smem round-trip, no extra sync),
//      entries written to smem in REVERSED blend order (front-to-back).
//   3. ONE __syncthreads.
//   4. Front-to-back transmittance blend; u/v per pixel via independent FMA.
//   5. Composite with prefetched canvas: out = acc + canvas*T.
// ---------------------------------------------------------------------------
__global__ void __launch_bounds__(64)
render_kernel(const float* __restrict__ param,
              const int*   __restrict__ decision,
              const float* __restrict__ canvas,
              float*       __restrict__ out) {
    __shared__ float4 sA[4 * NSTROKE];   // (C, S, U0', V0')  [scaled by 25]
    __shared__ float4 sB[4 * NSTROKE];   // (W, H, dS, dC)    [scaled by 25]
    __shared__ float4 sC[4 * NSTROKE];   // (cr, cg, cb, -)
    __shared__ int    sTot;

    const int a = blockIdx.y;            // padded cell row: Y in [16a, 16a+16)
    const int b = blockIdx.x;
    const int tx  = threadIdx.x;         // 0..15
    const int ty  = threadIdx.y;         // 0..3
    const int tid = ty * 16 + tx;

    // --- 1: canvas prefetch (earliest possible issue) ---
    const int x  = 16 * b + tx - 8;      // q = 8
    const int y0 = 16 * a + ty - 8;
    const bool vx = (unsigned)x < (unsigned)IMG;
    float cR[4], cG[4], cB[4];
    int   idx[4];
    bool  vv[4];
    #pragma unroll
    for (int k = 0; k < 4; k++) {
        int y = y0 + 4 * k;
        idx[k] = y * IMG + x;
        vv[k]  = vx && ((unsigned)y < (unsigned)IMG);
        cR[k] = cG[k] = cB[k] = 0.f;
        if (vv[k]) {
            cR[k] = canvas[idx[k]];
            cG[k] = canvas[PLANE + idx[k]];
            cB[k] = canvas[2 * PLANE + idx[k]];
        }
    }

    // --- 2: warp-synchronous staging (warp 0, lanes 0..19) ---
    if (tid < 32) {
        const int lane = tid;
        const int PR[4] = {0, 1, 1, 0};
        const int PC[4] = {0, 1, 0, 1};
        int p = 0, i = 0, r = 0, c = 0, t = 0;
        bool valid = false;
        int dec[NSTROKE];
        #pragma unroll
        for (int j = 0; j < NSTROKE; j++) dec[j] = 0;

        if (lane < 4 * NSTROKE) {
            p = lane / NSTROKE; i = lane - p * NSTROKE;
            r = (((a - 1) & 1) == PR[p]) ? (a - 1) : a;
            c = (((b - 1) & 1) == PC[p]) ? (b - 1) : b;
            valid = ((unsigned)r < 64u) && ((unsigned)c < 64u);
            t = r * GRID_T + c;
            if (valid) {
                #pragma unroll
                for (int j = 0; j < NSTROKE; j++)
                    dec[j] = decision[t * NSTROKE + j];
            }
        }
        int cnt = 0;
        #pragma unroll
        for (int j = 0; j < NSTROKE; j++) cnt += (dec[j] != 0);

        const int c0 = __shfl_sync(0xffffffffu, cnt, 0);
        const int c1 = __shfl_sync(0xffffffffu, cnt, 5);
        const int c2 = __shfl_sync(0xffffffffu, cnt, 10);
        const int c3 = __shfl_sync(0xffffffffu, cnt, 15);
        const int tot = c0 + c1 + c2 + c3;
        if (lane == 0) sTot = tot;

        if (lane < 4 * NSTROKE && dec[i] != 0) {
            int pos = 0;
            #pragma unroll
            for (int j = 0; j < NSTROKE; j++) pos += (j < i) && (dec[j] != 0);
            int base = ((p > 0) ? c0 : 0) + ((p > 1) ? c1 : 0) + ((p > 2) ? c2 : 0);
            int e = tot - 1 - (base + pos);      // reversed => front-to-back

            const float* q = param + (size_t)(t * NSTROKE + i) * 12;
            float p8[8];
            #pragma unroll
            for (int k = 0; k < 8; k++)
                p8[k] = __fdividef(1.0f, 1.0f + __expf(-q[k]));  // sigmoid

            float x0 = p8[0], yc = p8[1];
            float W = 12.5f * fmaxf(p8[2], 0.01f);   // 25 * (wd/2)
            float H = 12.5f * fmaxf(p8[3], 0.01f);
            float th = p8[4] * 3.14159265358979323846f;
            float st, ct;
            __sincosf(th, &st, &ct);

            float C  = 25.0f * ct, S = 25.0f * st;
            float U0 = -(x0 * C + yc * S);
            float V0 =  (x0 * S - yc * C);

            // fold per-pass tile offset into U0/V0
            float ox = ((float)(16 * (b - c)) + 0.5f) * 0.03125f;
            float oy = ((float)(16 * (a - r)) + 0.5f) * 0.03125f;
            float U0p = fmaf(ox, C, fmaf(oy, S, U0));
            float V0p = fmaf(oy, C, fmaf(-ox, S, V0));

            sA[e] = make_float4(C, S, U0p, V0p);
            sB[e] = make_float4(W, H, 0.125f * S, 0.125f * C);
            sC[e] = make_float4(p8[5], p8[6], p8[7], 0.f);
        }
    }
    __syncthreads();

    const int tot = sTot;
    const float gx = (float)tx * 0.03125f;
    const float gy = (float)ty * 0.03125f;

    float aR[4] = {0.f, 0.f, 0.f, 0.f};
    float aG[4] = {0.f, 0.f, 0.f, 0.f};
    float aB[4] = {0.f, 0.f, 0.f, 0.f};
    float T[4]  = {1.f, 1.f, 1.f, 1.f};

    // --- 4: front-to-back blend, independent u/v per pixel ---
    for (int e = 0; e < tot; e++) {
        float4 A  = sA[e];
        float4 B  = sB[e];
        float4 Cc = sC[e];

        float u0 = fmaf(gx, A.x, fmaf(gy, A.y, A.z));
        float v0 = fmaf(gy, A.x, fmaf(-gx, A.y, A.w));

        #pragma unroll
        for (int k = 0; k < 4; k++) {
            float kf = (float)k;
            float u = fmaf(kf, B.z, u0);        // u0 + k*0.125*S (independent)
            float v = fmaf(kf, B.w, v0);
            float t1 = tanh_(B.x - fabsf(u));
            float t2 = tanh_(B.y - fabsf(v));
            float h1 = fmaf(t1, 0.5f, 0.5f);
            float h2 = fmaf(t2, 0.5f, 0.5f);
            float aT = h1 * h2 * T[k];          // alpha * transmittance
            aR[k] = fmaf(aT, Cc.x, aR[k]);
            aG[k] = fmaf(aT, Cc.y, aG[k]);
            aB[k] = fmaf(aT, Cc.z, aB[k]);
            T[k] -= aT;
        }
    }

    // --- 5: composite with prefetched canvas ---
    #pragma unroll
    for (int k = 0; k < 4; k++) {
        if (vv[k]) {
            out[idx[k]]             = fmaf(cR[k], T[k], aR[k]);
            out[PLANE + idx[k]]     = fmaf(cG[k], T[k], aG[k]);
            out[2 * PLANE + idx[k]] = fmaf(cB[k], T[k], aB[k]);
        }
    }
}

// ---------------------------------------------------------------------------
extern "C" void kernel_launch(void* const* d_in, const int* in_sizes, int n_in,
                              void* d_out, int out_size) {
    const float* param    = (const float*)d_in[0];   // (1,64,64,5,12) f32
    const int*   decision = (const int*)  d_in[1];   // (1,64,64,5)    i32
    const float* canvas   = (const float*)d_in[2];   // (1,3,1024,1024) f32
    float*       out      = (float*)d_out;           // (1,3,1024,1024) f32

    dim3 bs(16, 4);          // 64 threads, 4 px/thread
    dim3 gs(65, 65);         // padded 1040x1040 in 16x16 cells
    render_kernel<<<gs, bs>>>(param, decision, canvas, out);
}